// round 10
// baseline (speedup 1.0000x reference)
#include <cuda_runtime.h>

// GRU_67714454389230: 2-layer GRU (H=12, IN=18) + fc(12->1), B=4096, T=512.
// Round 10 = Round 9 resubmitted (R9 bench died on infra, no data).
//  - gi scratch row-major [b*SEQ+t][u] float4: ONE contiguous LDG.128 per
//    batch-step in the scan (R8's 4 divergent plane-LDGs drove L1 to 79%).
//  - gi0 kernel: (row,u)-per-lane mapping (384 thr = 32 rows x 12 units),
//    per-u weights in registers, perfectly coalesced output STGs.
//  - r/z gate pre-scaling by 0.5 everywhere -> sigmoid = fma(tanh(acc),.5,.5),
//    no FMUL on the MUFU critical chains.

static constexpr int IN_DIM = 18;
static constexpr int HID    = 12;
static constexpr int BATCH  = 4096;
static constexpr int SEQ    = 512;
static constexpr size_t NROWS = (size_t)BATCH * SEQ;   // 2,097,152

typedef unsigned long long ull;

// row-major: g_gi0[(b*SEQ+t)*12 + u] = float4(0.5*gi_r, 0.5*gi_z, gi_n, 0)
__device__ float4 g_gi0[NROWS * HID];

// ---------------- helpers ----------------
__device__ __forceinline__ ull ffma2(ull a, ull b, ull c) {
    ull d;
    asm("fma.rn.f32x2 %0, %1, %2, %3;" : "=l"(d) : "l"(a), "l"(b), "l"(c));
    return d;
}
__device__ __forceinline__ float f2sum(ull v) {
    float lo, hi;
    asm("mov.b64 {%0, %1}, %2;" : "=f"(lo), "=f"(hi) : "l"(v));
    return lo + hi;
}
__device__ __forceinline__ ull fpack(float lo, float hi) {
    ull v;
    asm("mov.b64 %0, {%1, %2};" : "=l"(v) : "f"(lo), "f"(hi));
    return v;
}
__device__ __forceinline__ float tanhapx(float x) {
    float y;
    asm("tanh.approx.f32 %0, %1;" : "=f"(y) : "f"(x));
    return y;
}
// input is ALREADY 0.5*(pre-activation)
__device__ __forceinline__ float sig_pre(float half_x) {
    return fmaf(tanhapx(half_x), 0.5f, 0.5f);
}

// ---------------- kernel 1: gi0 = x @ W_ih0^T + b_ih0 (r,z scaled by 0.5) ---
// 384 threads: u = tid%12 (unit), roff = tid/12 (0..31). Block does 256 rows.
static constexpr int GI_ROWS = 256;

__global__ __launch_bounds__(384, 2)
void gi0_kernel(const float* __restrict__ x,
                const float* __restrict__ w_ih0,
                const float* __restrict__ b_ih0)
{
    __shared__ ull s_xu[GI_ROWS * 11];   // 9 ull pairs/row, pad to 11

    const int tid  = threadIdx.x;
    const int u    = tid % 12;
    const int roff = tid / 12;

    // stage x rows (linear ull copy with padded destination)
    const size_t row0 = (size_t)blockIdx.x * GI_ROWS;
    const ull* xg = (const ull*)(x + row0 * IN_DIM);
    for (int i = tid; i < GI_ROWS * 9; i += 384) {
        const int r = i / 9, p = i % 9;
        s_xu[r * 11 + p] = xg[i];
    }

    // per-u weight rows in registers; r,z rows (and biases) pre-scaled by 0.5
    ull w[3][9];
    float bias[3];
#pragma unroll
    for (int g = 0; g < 3; ++g) {
        const float s = (g < 2) ? 0.5f : 1.0f;
        const float* wr = w_ih0 + (g * HID + u) * IN_DIM;
#pragma unroll
        for (int k = 0; k < 9; ++k)
            w[g][k] = fpack(wr[2 * k] * s, wr[2 * k + 1] * s);
        bias[g] = b_ih0[g * HID + u] * s;
    }
    __syncthreads();

    float4* og = g_gi0 + row0 * HID;
#pragma unroll 1
    for (int it = 0; it < GI_ROWS / 32; ++it) {
        const int r = it * 32 + roff;
        ull xr[9];
        const ull* xrow = s_xu + r * 11;
#pragma unroll
        for (int k = 0; k < 9; ++k) xr[k] = xrow[k];
        float res[3];
#pragma unroll
        for (int g = 0; g < 3; ++g) {
            ull acc = fpack(bias[g], 0.0f);
#pragma unroll
            for (int k = 0; k < 9; ++k) acc = ffma2(xr[k], w[g][k], acc);
            res[g] = f2sum(acc);
        }
        og[(size_t)r * HID + u] = make_float4(res[0], res[1], res[2], 0.0f);
    }
}

// ---------------- kernel 2: recurrent scan (layer-pipelined) ----------------
// 32-thread blocks: 2 groups of 16 lanes, 2 batches per group -> 4 batches.
static constexpr int S_THREADS = 32;
static constexpr int S_GRID    = BATCH / 4;   // 1024 blocks

__global__ __launch_bounds__(S_THREADS, 8)
void gru_scan_kernel(const float* __restrict__ w_hh0, const float* __restrict__ b_hh0,
                     const float* __restrict__ w_ih1, const float* __restrict__ w_hh1,
                     const float* __restrict__ b_ih1, const float* __restrict__ b_hh1,
                     const float* __restrict__ fc_w, const float* __restrict__ fc_b,
                     float* __restrict__ out)
{
    __shared__ __align__(16) float s_h1[2][2][HID];   // [group][batch][unit]
    __shared__ __align__(16) float s_h2[2][2][HID];
    __shared__ float s_fcw[HID];

    const int tid   = threadIdx.x;
    const int grp_l = tid >> 4;
    const int sub   = tid & 15;
    const int u     = (sub < HID) ? sub : HID - 1;
    const int bA    = blockIdx.x * 4 + grp_l * 2;
    const int bB    = bA + 1;

    if (tid < HID) s_fcw[tid] = fc_w[tid];

    // All recurrent weights in registers (f32x2 pairs); r,z rows scaled 0.5.
    ull whh0[3][6], wih1[3][6], whh1[3][6];
#pragma unroll
    for (int g = 0; g < 3; ++g) {
        const float s = (g < 2) ? 0.5f : 1.0f;
        const float* p0 = w_hh0 + (g * HID + u) * HID;
        const float* p1 = w_ih1 + (g * HID + u) * HID;
        const float* p2 = w_hh1 + (g * HID + u) * HID;
#pragma unroll
        for (int i = 0; i < 6; ++i) {
            whh0[g][i] = fpack(p0[2*i] * s, p0[2*i+1] * s);
            wih1[g][i] = fpack(p1[2*i] * s, p1[2*i+1] * s);
            whh1[g][i] = fpack(p2[2*i] * s, p2[2*i+1] * s);
        }
    }

    const float bh0r = b_hh0[u] * 0.5f;
    const float bh0z = b_hh0[HID + u] * 0.5f;
    const float bh0n = b_hh0[2 * HID + u];
    const ull pbh0n = fpack(bh0n, 0.0f);
    const ull pb2r  = fpack((b_ih1[u]       + b_hh1[u])       * 0.5f, 0.0f);
    const ull pb2z  = fpack((b_ih1[HID + u] + b_hh1[HID + u]) * 0.5f, 0.0f);
    const ull pb2in = fpack(b_ih1[2 * HID + u], 0.0f);
    const ull pb2hn = fpack(b_hh1[2 * HID + u], 0.0f);
    const float fcb = fc_b[0];

    // row-major gi pointers: step stride = HID float4s (192B, group-contiguous)
    const float4* gpA = g_gi0 + (size_t)bA * SEQ * HID + u;
    const float4* gpB = g_gi0 + (size_t)bB * SEQ * HID + u;

    ull H1A[6], H1B[6], H2A[6], H2B[6];
#pragma unroll
    for (int i = 0; i < 6; ++i) { H1A[i] = H1B[i] = H2A[i] = H2B[i] = 0ull; }
    float hp1A, hp1B, hp2A = 0.0f, hp2B = 0.0f;
    __syncthreads();

    // ---- prologue: h1[0] = GRU1(gi0[0], 0) ----
    {
        const float4 gA = gpA[0], gB = gpB[0];
        const float rA = sig_pre(gA.x + bh0r);
        const float rB = sig_pre(gB.x + bh0r);
        const float zA = sig_pre(gA.y + bh0z);
        const float zB = sig_pre(gB.y + bh0z);
        const float nA = tanhapx(fmaf(rA, bh0n, gA.z));
        const float nB = tanhapx(fmaf(rB, bh0n, gB.z));
        hp1A = nA - zA * nA;
        hp1B = nB - zB * nB;
        if (sub < HID) { s_h1[grp_l][0][u] = hp1A; s_h1[grp_l][1][u] = hp1B; }
        __syncwarp();
        const ulonglong2* pa = (const ulonglong2*)s_h1[grp_l][0];
        const ulonglong2* pb = (const ulonglong2*)s_h1[grp_l][1];
        const ulonglong2 a0 = pa[0], a1 = pa[1], a2 = pa[2];
        const ulonglong2 b0 = pb[0], b1 = pb[1], b2 = pb[2];
        H1A[0] = a0.x; H1A[1] = a0.y; H1A[2] = a1.x;
        H1A[3] = a1.y; H1A[4] = a2.x; H1A[5] = a2.y;
        H1B[0] = b0.x; H1B[1] = b0.y; H1B[2] = b1.x;
        H1B[3] = b1.y; H1B[4] = b2.x; H1B[5] = b2.y;
    }

    // gi for t+1 = 1 (consumed by layer1 inside iteration t=0)
    float4 gA = gpA[HID], gB = gpB[HID];

#pragma unroll 1
    for (int t = 0; t < SEQ; ++t) {
        const size_t tn = (size_t)((t + 2 < SEQ) ? (t + 2) : SEQ - 1) * HID;
        const float4 gA_n = gpA[tn];
        const float4 gB_n = gpB[tn];

        // ======== layer 2 @ t (H1=h1[t], H2=h2[t-1])  +  layer 1 @ t+1 ========
        ull prA = pb2r, pzA = pb2z, pnA = pb2hn, piA = pb2in;
        ull prB = pb2r, pzB = pb2z, pnB = pb2hn, piB = pb2in;
        ull qrA = fpack(gA.x, bh0r), qzA = fpack(gA.y, bh0z), qnA = pbh0n;
        ull qrB = fpack(gB.x, bh0r), qzB = fpack(gB.y, bh0z), qnB = pbh0n;

#pragma unroll
        for (int i = 0; i < 6; ++i) {
            prA = ffma2(H2A[i], whh1[0][i], prA); prB = ffma2(H2B[i], whh1[0][i], prB);
            pzA = ffma2(H2A[i], whh1[1][i], pzA); pzB = ffma2(H2B[i], whh1[1][i], pzB);
            pnA = ffma2(H2A[i], whh1[2][i], pnA); pnB = ffma2(H2B[i], whh1[2][i], pnB);
            prA = ffma2(H1A[i], wih1[0][i], prA); prB = ffma2(H1B[i], wih1[0][i], prB);
            pzA = ffma2(H1A[i], wih1[1][i], pzA); pzB = ffma2(H1B[i], wih1[1][i], pzB);
            piA = ffma2(H1A[i], wih1[2][i], piA); piB = ffma2(H1B[i], wih1[2][i], piB);
            qrA = ffma2(H1A[i], whh0[0][i], qrA); qrB = ffma2(H1B[i], whh0[0][i], qrB);
            qzA = ffma2(H1A[i], whh0[1][i], qzA); qzB = ffma2(H1B[i], whh0[1][i], qzB);
            qnA = ffma2(H1A[i], whh0[2][i], qnA); qnB = ffma2(H1B[i], whh0[2][i], qnB);
        }

        // layer2 activations -> h2[t]
        const float r2A = sig_pre(f2sum(prA));
        const float r2B = sig_pre(f2sum(prB));
        const float z2A = sig_pre(f2sum(pzA));
        const float z2B = sig_pre(f2sum(pzB));
        const float n2A = tanhapx(fmaf(r2A, f2sum(pnA), f2sum(piA)));
        const float n2B = tanhapx(fmaf(r2B, f2sum(pnB), f2sum(piB)));
        const float hn2A = fmaf(z2A, hp2A - n2A, n2A);
        const float hn2B = fmaf(z2B, hp2B - n2B, n2B);
        hp2A = hn2A; hp2B = hn2B;

        // layer1 activations -> h1[t+1]
        const float r1A = sig_pre(f2sum(qrA));
        const float r1B = sig_pre(f2sum(qrB));
        const float z1A = sig_pre(f2sum(qzA));
        const float z1B = sig_pre(f2sum(qzB));
        const float n1A = tanhapx(fmaf(r1A, f2sum(qnA), gA.z));
        const float n1B = tanhapx(fmaf(r1B, f2sum(qnB), gB.z));
        const float hn1A = fmaf(z1A, hp1A - n1A, n1A);
        const float hn1B = fmaf(z1B, hp1B - n1B, n1B);
        hp1A = hn1A; hp1B = hn1B;

        // ======== combined exchange ========
        if (sub < HID) {
            s_h1[grp_l][0][u] = hn1A; s_h1[grp_l][1][u] = hn1B;
            s_h2[grp_l][0][u] = hn2A; s_h2[grp_l][1][u] = hn2B;
        }
        __syncwarp();
        {
            const ulonglong2* pa = (const ulonglong2*)s_h1[grp_l][0];
            const ulonglong2* pb = (const ulonglong2*)s_h1[grp_l][1];
            const ulonglong2 a0 = pa[0], a1 = pa[1], a2 = pa[2];
            const ulonglong2 b0 = pb[0], b1 = pb[1], b2 = pb[2];
            H1A[0] = a0.x; H1A[1] = a0.y; H1A[2] = a1.x;
            H1A[3] = a1.y; H1A[4] = a2.x; H1A[5] = a2.y;
            H1B[0] = b0.x; H1B[1] = b0.y; H1B[2] = b1.x;
            H1B[3] = b1.y; H1B[4] = b2.x; H1B[5] = b2.y;
        }
        {
            const ulonglong2* pa = (const ulonglong2*)s_h2[grp_l][0];
            const ulonglong2* pb = (const ulonglong2*)s_h2[grp_l][1];
            const ulonglong2 a0 = pa[0], a1 = pa[1], a2 = pa[2];
            const ulonglong2 b0 = pb[0], b1 = pb[1], b2 = pb[2];
            H2A[0] = a0.x; H2A[1] = a0.y; H2A[2] = a1.x;
            H2A[3] = a1.y; H2A[4] = a2.x; H2A[5] = a2.y;
            H2B[0] = b0.x; H2B[1] = b0.y; H2B[2] = b1.x;
            H2B[3] = b1.y; H2B[4] = b2.x; H2B[5] = b2.y;
        }

        // ======== fc(h2[t]) on idle lanes 12 (A) / 13 (B) ========
        if (sub >= 12 && sub < 14) {
            const ull* hh = (sub == 12) ? H2A : H2B;
            ull acc = fpack(fcb, 0.0f);
#pragma unroll
            for (int i = 0; i < 6; ++i)
                acc = ffma2(hh[i], *(const ull*)&s_fcw[2 * i], acc);
            out[(size_t)((sub == 12) ? bA : bB) * SEQ + t] = f2sum(acc);
        }

        gA = gA_n; gB = gB_n;
    }
}

extern "C" void kernel_launch(void* const* d_in, const int* in_sizes, int n_in,
                              void* d_out, int out_size) {
    const float* x     = (const float*)d_in[0];
    const float* w_ih0 = (const float*)d_in[1];
    const float* w_hh0 = (const float*)d_in[2];
    const float* b_ih0 = (const float*)d_in[3];
    const float* b_hh0 = (const float*)d_in[4];
    const float* w_ih1 = (const float*)d_in[5];
    const float* w_hh1 = (const float*)d_in[6];
    const float* b_ih1 = (const float*)d_in[7];
    const float* b_hh1 = (const float*)d_in[8];
    const float* fc_w  = (const float*)d_in[9];
    const float* fc_b  = (const float*)d_in[10];
    float* out = (float*)d_out;

    gi0_kernel<<<(int)(NROWS / GI_ROWS), 384>>>(x, w_ih0, b_ih0);
    gru_scan_kernel<<<S_GRID, S_THREADS>>>(w_hh0, b_hh0, w_ih1, w_hh1,
                                           b_ih1, b_hh1, fc_w, fc_b, out);
}

// round 11
// speedup vs baseline: 1.0595x; 1.0595x over previous
#include <cuda_runtime.h>

// GRU_67714454389230: 2-layer GRU (H=12, IN=18) + fc(12->1), B=4096, T=512.
// Round 11: R7 plane-gi + R7 gi0 (both measured-best) + R8 layer-pipelining +
// R9 pre-scaling, and the new lever: 1 batch per 16-lane group -> 2048 warps
// (3.5/SMSP, 2x latency hiding). w_hh1 in smem to fit 146-reg cap at 14
// blocks/SM (single wave: 2048 blocks <= 148*14).

static constexpr int IN_DIM = 18;
static constexpr int HID    = 12;
static constexpr int BATCH  = 4096;
static constexpr int SEQ    = 512;
static constexpr size_t NROWS = (size_t)BATCH * SEQ;   // 2,097,152

typedef unsigned long long ull;

// plane layout: g_gi0[u*NROWS + (b*SEQ+t)] = float4(0.5*gi_r, 0.5*gi_z, gi_n, 0)
__device__ float4 g_gi0[HID * NROWS];

// ---------------- helpers ----------------
__device__ __forceinline__ ull ffma2(ull a, ull b, ull c) {
    ull d;
    asm("fma.rn.f32x2 %0, %1, %2, %3;" : "=l"(d) : "l"(a), "l"(b), "l"(c));
    return d;
}
__device__ __forceinline__ float f2sum(ull v) {
    float lo, hi;
    asm("mov.b64 {%0, %1}, %2;" : "=f"(lo), "=f"(hi) : "l"(v));
    return lo + hi;
}
__device__ __forceinline__ ull fpack(float lo, float hi) {
    ull v;
    asm("mov.b64 %0, {%1, %2};" : "=l"(v) : "f"(lo), "f"(hi));
    return v;
}
__device__ __forceinline__ float tanhapx(float x) {
    float y;
    asm("tanh.approx.f32 %0, %1;" : "=f"(y) : "f"(x));
    return y;
}
// input is ALREADY 0.5*(pre-activation)
__device__ __forceinline__ float sig_pre(float half_x) {
    return fmaf(tanhapx(half_x), 0.5f, 0.5f);
}

// ---------------- kernel 1: gi0 (R7 version + 0.5 pre-scale on r,z) --------
static constexpr int GI_ROWS = 512;

__global__ __launch_bounds__(128, 4)
void gi0_kernel(const float* __restrict__ x,
                const float* __restrict__ w_ih0,
                const float* __restrict__ b_ih0)
{
    __shared__ ull   s_xu[GI_ROWS * 11];   // 9 pairs + pad to 11 -> conflict-free
    __shared__ ull   s_w[36][9];
    __shared__ float s_b[36];

    const int tid = threadIdx.x;
    for (int i = tid; i < 36 * 9; i += 128) {
        const int j = i / 9, k = i % 9;
        const float s = (j < 24) ? 0.5f : 1.0f;     // r,z rows scaled
        const float* wp = w_ih0 + j * IN_DIM + 2 * k;
        s_w[j][k] = fpack(wp[0] * s, wp[1] * s);
    }
    if (tid < 36) s_b[tid] = b_ih0[tid] * ((tid < 24) ? 0.5f : 1.0f);

    const size_t row0 = (size_t)blockIdx.x * GI_ROWS;
    const ull* xg = (const ull*)(x + row0 * IN_DIM);
    for (int i = tid; i < GI_ROWS * 9; i += 128) {
        const int r = i / 9, p = i % 9;
        s_xu[r * 11 + p] = xg[i];
    }
    __syncthreads();

    ull xp[4][9];
#pragma unroll
    for (int j = 0; j < 4; ++j) {
        const ull* row = s_xu + (tid + j * 128) * 11;
#pragma unroll
        for (int k = 0; k < 9; ++k) xp[j][k] = row[k];
    }

#pragma unroll
    for (int u = 0; u < HID; ++u) {
        float res[4][3];
#pragma unroll
        for (int g = 0; g < 3; ++g) {
            const int jrow = g * HID + u;
            ull w[9];
#pragma unroll
            for (int k = 0; k < 9; ++k) w[k] = s_w[jrow][k];
            const float b = s_b[jrow];
#pragma unroll
            for (int j = 0; j < 4; ++j) {
                ull acc = fpack(b, 0.0f);
#pragma unroll
                for (int k = 0; k < 9; ++k) acc = ffma2(xp[j][k], w[k], acc);
                res[j][g] = f2sum(acc);
            }
        }
        float4* plane = g_gi0 + (size_t)u * NROWS + row0;
#pragma unroll
        for (int j = 0; j < 4; ++j)
            plane[tid + j * 128] = make_float4(res[j][0], res[j][1], res[j][2], 0.0f);
    }
}

// ---------------- kernel 2: recurrent scan ----------------
// 32-thread blocks = 1 warp = 2 groups of 16 lanes, ONE batch per group.
// 2048 blocks -> 3.5 warps/SMSP (2x the latency hiding of R7-R10).
static constexpr int S_THREADS = 32;
static constexpr int S_GRID    = BATCH / 2;   // 2048 blocks

__global__ __launch_bounds__(S_THREADS, 14)
void gru_scan_kernel(const float* __restrict__ w_hh0, const float* __restrict__ b_hh0,
                     const float* __restrict__ w_ih1, const float* __restrict__ w_hh1,
                     const float* __restrict__ b_ih1, const float* __restrict__ b_hh1,
                     const float* __restrict__ fc_w, const float* __restrict__ fc_b,
                     float* __restrict__ out)
{
    __shared__ ull s_whh1[3][6][HID];                 // r,z rows pre-scaled 0.5
    __shared__ __align__(16) float s_h1[2][HID];      // [group][unit]
    __shared__ __align__(16) float s_h2[2][HID];
    __shared__ float s_fcw[HID];

    const int tid   = threadIdx.x;
    const int grp_l = tid >> 4;
    const int sub   = tid & 15;
    const int u     = (sub < HID) ? sub : HID - 1;
    const int batch = blockIdx.x * 2 + grp_l;

    if (tid < HID) s_fcw[tid] = fc_w[tid];
    for (int i = tid; i < 36; i += S_THREADS) {
        const int g = i / HID, uu = i % HID;
        const float s = (g < 2) ? 0.5f : 1.0f;
        const float* wr = w_hh1 + (g * HID + uu) * HID;
#pragma unroll
        for (int k = 0; k < 6; ++k)
            s_whh1[g][k][uu] = fpack(wr[2*k] * s, wr[2*k+1] * s);
    }

    // whh0 + wih1 in registers (f32x2 pairs); r,z rows scaled 0.5.
    ull whh0[3][6], wih1[3][6];
#pragma unroll
    for (int g = 0; g < 3; ++g) {
        const float s = (g < 2) ? 0.5f : 1.0f;
        const float* p0 = w_hh0 + (g * HID + u) * HID;
        const float* p1 = w_ih1 + (g * HID + u) * HID;
#pragma unroll
        for (int i = 0; i < 6; ++i) {
            whh0[g][i] = fpack(p0[2*i] * s, p0[2*i+1] * s);
            wih1[g][i] = fpack(p1[2*i] * s, p1[2*i+1] * s);
        }
    }

    const float bh0r = b_hh0[u] * 0.5f;
    const float bh0z = b_hh0[HID + u] * 0.5f;
    const float bh0n = b_hh0[2 * HID + u];
    const ull pbh0n = fpack(bh0n, 0.0f);
    const ull pb2r  = fpack((b_ih1[u]       + b_hh1[u])       * 0.5f, 0.0f);
    const ull pb2z  = fpack((b_ih1[HID + u] + b_hh1[HID + u]) * 0.5f, 0.0f);
    const ull pb2in = fpack(b_ih1[2 * HID + u], 0.0f);
    const ull pb2hn = fpack(b_hh1[2 * HID + u], 0.0f);
    const float fcb = fc_b[0];

    // plane gi pointer: per-lane contiguous stream (16B/step -> L1-hit heavy)
    const float4* gp = g_gi0 + (size_t)u * NROWS + (size_t)batch * SEQ;

    ull H1[6], H2[6];
#pragma unroll
    for (int i = 0; i < 6; ++i) { H1[i] = H2[i] = 0ull; }
    float hp1, hp2 = 0.0f;
    __syncwarp();

    // ---- prologue: h1[0] = GRU1(gi0[0], 0) ----
    {
        const float4 g0 = gp[0];
        const float r = sig_pre(g0.x + bh0r);
        const float z = sig_pre(g0.y + bh0z);
        const float n = tanhapx(fmaf(r, bh0n, g0.z));
        hp1 = n - z * n;
        if (sub < HID) s_h1[grp_l][u] = hp1;
        __syncwarp();
        const ulonglong2* pa = (const ulonglong2*)s_h1[grp_l];
        const ulonglong2 a0 = pa[0], a1 = pa[1], a2 = pa[2];
        H1[0] = a0.x; H1[1] = a0.y; H1[2] = a1.x;
        H1[3] = a1.y; H1[4] = a2.x; H1[5] = a2.y;
    }

    float4 gc = gp[1];   // gi for t+1=1

#pragma unroll 1
    for (int t = 0; t < SEQ; ++t) {
        const int tn = (t + 2 < SEQ) ? (t + 2) : SEQ - 1;
        const float4 gn = gp[tn];

        // ======== layer 2 @ t (H1=h1[t], H2=h2[t-1])  +  layer 1 @ t+1 ========
        ull pr = pb2r, pz = pb2z, pn = pb2hn, pi = pb2in;
        ull qr = fpack(gc.x, bh0r), qz = fpack(gc.y, bh0z), qn = pbh0n;

#pragma unroll
        for (int i = 0; i < 6; ++i) {
            pr = ffma2(H2[i], s_whh1[0][i][u], pr);
            pz = ffma2(H2[i], s_whh1[1][i][u], pz);
            pn = ffma2(H2[i], s_whh1[2][i][u], pn);
            pr = ffma2(H1[i], wih1[0][i], pr);
            pz = ffma2(H1[i], wih1[1][i], pz);
            pi = ffma2(H1[i], wih1[2][i], pi);
            qr = ffma2(H1[i], whh0[0][i], qr);
            qz = ffma2(H1[i], whh0[1][i], qz);
            qn = ffma2(H1[i], whh0[2][i], qn);
        }

        // layer2 activations -> h2[t]
        const float r2 = sig_pre(f2sum(pr));
        const float z2 = sig_pre(f2sum(pz));
        const float n2 = tanhapx(fmaf(r2, f2sum(pn), f2sum(pi)));
        const float hn2 = fmaf(z2, hp2 - n2, n2);
        hp2 = hn2;

        // layer1 activations -> h1[t+1]
        const float r1 = sig_pre(f2sum(qr));
        const float z1 = sig_pre(f2sum(qz));
        const float n1 = tanhapx(fmaf(r1, f2sum(qn), gc.z));
        const float hn1 = fmaf(z1, hp1 - n1, n1);
        hp1 = hn1;

        // ======== combined exchange ========
        if (sub < HID) {
            s_h1[grp_l][u] = hn1;
            s_h2[grp_l][u] = hn2;
        }
        __syncwarp();
        {
            const ulonglong2* pa = (const ulonglong2*)s_h1[grp_l];
            const ulonglong2 a0 = pa[0], a1 = pa[1], a2 = pa[2];
            H1[0] = a0.x; H1[1] = a0.y; H1[2] = a1.x;
            H1[3] = a1.y; H1[4] = a2.x; H1[5] = a2.y;
        }
        {
            const ulonglong2* pa = (const ulonglong2*)s_h2[grp_l];
            const ulonglong2 a0 = pa[0], a1 = pa[1], a2 = pa[2];
            H2[0] = a0.x; H2[1] = a0.y; H2[2] = a1.x;
            H2[3] = a1.y; H2[4] = a2.x; H2[5] = a2.y;
        }

        // ======== fc(h2[t]) on idle lane 12 ========
        if (sub == 12) {
            ull acc = fpack(fcb, 0.0f);
#pragma unroll
            for (int i = 0; i < 6; ++i)
                acc = ffma2(H2[i], *(const ull*)&s_fcw[2 * i], acc);
            out[(size_t)batch * SEQ + t] = f2sum(acc);
        }

        gc = gn;
    }
}

extern "C" void kernel_launch(void* const* d_in, const int* in_sizes, int n_in,
                              void* d_out, int out_size) {
    const float* x     = (const float*)d_in[0];
    const float* w_ih0 = (const float*)d_in[1];
    const float* w_hh0 = (const float*)d_in[2];
    const float* b_ih0 = (const float*)d_in[3];
    const float* b_hh0 = (const float*)d_in[4];
    const float* w_ih1 = (const float*)d_in[5];
    const float* w_hh1 = (const float*)d_in[6];
    const float* b_ih1 = (const float*)d_in[7];
    const float* b_hh1 = (const float*)d_in[8];
    const float* fc_w  = (const float*)d_in[9];
    const float* fc_b  = (const float*)d_in[10];
    float* out = (float*)d_out;

    gi0_kernel<<<(int)(NROWS / GI_ROWS), 128>>>(x, w_ih0, b_ih0);
    gru_scan_kernel<<<S_GRID, S_THREADS>>>(w_hh0, b_hh0, w_ih1, w_hh1,
                                           b_ih1, b_hh1, fc_w, fc_b, out);
}

// round 12
// speedup vs baseline: 1.0981x; 1.0364x over previous
#include <cuda_runtime.h>

// GRU_67714454389230: 2-layer GRU (H=12, IN=18) + fc(12->1), B=4096, T=512.
// Round 12: R7 scan config (4 batches/warp, ALL weights in regs — measured
// best) + R8 layer-pipelining + R9 pre-scaling, plus the new lever:
// WARP-INTERLEAVED gi scratch [scanWarp][t][s][lane] so each scan step reads
// exactly 2 coalesced LDG.128 (512B each) instead of ~48 scattered lines.
// gi0 rewritten to emit this layout with coalesced STGs.

static constexpr int IN_DIM = 18;
static constexpr int HID    = 12;
static constexpr int BATCH  = 4096;
static constexpr int SEQ    = 512;
static constexpr int NWARP  = BATCH / 4;              // 1024 scan warps

typedef unsigned long long ull;

// [W][t][s][lane] : lane = grp*16 + u ; s selects batch A/B of the group.
// value = float4(0.5*gi_r, 0.5*gi_z, gi_n, 0) for batch 4W+2*grp+s, unit u.
__device__ float4 g_gi[(size_t)NWARP * SEQ * 2 * 32];

// ---------------- helpers ----------------
__device__ __forceinline__ ull ffma2(ull a, ull b, ull c) {
    ull d;
    asm("fma.rn.f32x2 %0, %1, %2, %3;" : "=l"(d) : "l"(a), "l"(b), "l"(c));
    return d;
}
__device__ __forceinline__ float f2sum(ull v) {
    float lo, hi;
    asm("mov.b64 {%0, %1}, %2;" : "=f"(lo), "=f"(hi) : "l"(v));
    return lo + hi;
}
__device__ __forceinline__ ull fpack(float lo, float hi) {
    ull v;
    asm("mov.b64 %0, {%1, %2};" : "=l"(v) : "f"(lo), "f"(hi));
    return v;
}
__device__ __forceinline__ float tanhapx(float x) {
    float y;
    asm("tanh.approx.f32 %0, %1;" : "=f"(y) : "f"(x));
    return y;
}
// input is ALREADY 0.5*(pre-activation)
__device__ __forceinline__ float sig_pre(float half_x) {
    return fmaf(tanhapx(half_x), 0.5f, 0.5f);
}

// ---------------- kernel 1: gi0 -> warp-interleaved layout ----------------
// One block per scan-warp W (1024 blocks, 128 threads = 4 warps).
// Block covers batches 4W..4W+3, all 512 t, in 4 chunks of 128 t.
// Thread lane (l = tid&31): grp=l>>4, u=min(l&15,11). Warp wid handles
// (tt,s) pairs p = wid + 4k. Writes are 512B-contiguous per (tt,s).
static constexpr int T_CHUNK = 128;

__global__ __launch_bounds__(128, 4)
void gi0_kernel(const float* __restrict__ x,
                const float* __restrict__ w_ih0,
                const float* __restrict__ b_ih0)
{
    __shared__ ull s_x[4 * T_CHUNK * 9];   // 4 batches x 128 t x 9 ull = 36 KB

    const int tid  = threadIdx.x;
    const int wid  = tid >> 5;
    const int lane = tid & 31;
    const int grp  = lane >> 4;
    const int sub  = lane & 15;
    const int u    = (sub < HID) ? sub : HID - 1;
    const int W    = blockIdx.x;

    // per-thread weights for unit u (r,z rows pre-scaled by 0.5)
    ull w[3][9];
    float bias[3];
#pragma unroll
    for (int g = 0; g < 3; ++g) {
        const float s = (g < 2) ? 0.5f : 1.0f;
        const float* wr = w_ih0 + (g * HID + u) * IN_DIM;
#pragma unroll
        for (int k = 0; k < 9; ++k)
            w[g][k] = fpack(wr[2 * k] * s, wr[2 * k + 1] * s);
        bias[g] = b_ih0[g * HID + u] * s;
    }

    float4* og = g_gi + (size_t)W * SEQ * 64;

#pragma unroll 1
    for (int c = 0; c < SEQ / T_CHUNK; ++c) {
        const int t0 = c * T_CHUNK;
        // stage x rows: 4 batches x 128 t x 9 ull
        for (int i = tid; i < 4 * T_CHUNK * 9; i += 128) {
            const int r = i / 9, p = i % 9;          // r = b_local*128 + tt
            const int b_local = r >> 7, tt = r & 127;
            s_x[i] = *(const ull*)(x + ((size_t)(4 * W + b_local) * SEQ + t0 + tt) * IN_DIM + 2 * p);
        }
        __syncthreads();

        // each warp: 64 (tt,s) pairs
#pragma unroll 1
        for (int k = 0; k < 64; ++k) {
            const int p  = wid + 4 * k;
            const int tt = p >> 1;
            const int s  = p & 1;
            const int b_local = 2 * grp + s;
            const ull* xr = s_x + (b_local * T_CHUNK + tt) * 9;
            ull xv[9];
#pragma unroll
            for (int q = 0; q < 9; ++q) xv[q] = xr[q];
            float res[3];
#pragma unroll
            for (int g = 0; g < 3; ++g) {
                ull acc = fpack(bias[g], 0.0f);
#pragma unroll
                for (int q = 0; q < 9; ++q) acc = ffma2(xv[q], w[g][q], acc);
                res[g] = f2sum(acc);
            }
            og[((size_t)(t0 + tt) * 2 + s) * 32 + lane] =
                make_float4(res[0], res[1], res[2], 0.0f);
        }
        __syncthreads();
    }
}

// ---------------- kernel 2: recurrent scan ----------------
// 1024 blocks x 32 threads. Warp = 2 groups x 2 batches (R7 config),
// all recurrent weights in registers, layer-pipelined (R8).
static constexpr int S_THREADS = 32;
static constexpr int S_GRID    = NWARP;   // 1024

__global__ __launch_bounds__(S_THREADS, 8)
void gru_scan_kernel(const float* __restrict__ w_hh0, const float* __restrict__ b_hh0,
                     const float* __restrict__ w_ih1, const float* __restrict__ w_hh1,
                     const float* __restrict__ b_ih1, const float* __restrict__ b_hh1,
                     const float* __restrict__ fc_w, const float* __restrict__ fc_b,
                     float* __restrict__ out)
{
    __shared__ __align__(16) float s_h1[2][2][HID];   // [group][batch][unit]
    __shared__ __align__(16) float s_h2[2][2][HID];
    __shared__ float s_fcw[HID];

    const int tid   = threadIdx.x;
    const int grp_l = tid >> 4;
    const int sub   = tid & 15;
    const int u     = (sub < HID) ? sub : HID - 1;
    const int W     = blockIdx.x;
    const int bA    = 4 * W + 2 * grp_l;
    const int bB    = bA + 1;

    if (tid < HID) s_fcw[tid] = fc_w[tid];

    // All recurrent weights in registers (f32x2 pairs); r,z rows scaled 0.5.
    ull whh0[3][6], wih1[3][6], whh1[3][6];
#pragma unroll
    for (int g = 0; g < 3; ++g) {
        const float s = (g < 2) ? 0.5f : 1.0f;
        const float* p0 = w_hh0 + (g * HID + u) * HID;
        const float* p1 = w_ih1 + (g * HID + u) * HID;
        const float* p2 = w_hh1 + (g * HID + u) * HID;
#pragma unroll
        for (int i = 0; i < 6; ++i) {
            whh0[g][i] = fpack(p0[2*i] * s, p0[2*i+1] * s);
            wih1[g][i] = fpack(p1[2*i] * s, p1[2*i+1] * s);
            whh1[g][i] = fpack(p2[2*i] * s, p2[2*i+1] * s);
        }
    }

    const float bh0r = b_hh0[u] * 0.5f;
    const float bh0z = b_hh0[HID + u] * 0.5f;
    const float bh0n = b_hh0[2 * HID + u];
    const ull pbh0n = fpack(bh0n, 0.0f);
    const ull pb2r  = fpack((b_ih1[u]       + b_hh1[u])       * 0.5f, 0.0f);
    const ull pb2z  = fpack((b_ih1[HID + u] + b_hh1[HID + u]) * 0.5f, 0.0f);
    const ull pb2in = fpack(b_ih1[2 * HID + u], 0.0f);
    const ull pb2hn = fpack(b_hh1[2 * HID + u], 0.0f);
    const float fcb = fc_b[0];

    // warp-interleaved gi: step t -> pw[t*64] (s=0, batch A), pw[t*64+32] (B)
    const float4* pw = g_gi + (size_t)W * SEQ * 64 + tid;

    ull H1A[6], H1B[6], H2A[6], H2B[6];
#pragma unroll
    for (int i = 0; i < 6; ++i) { H1A[i] = H1B[i] = H2A[i] = H2B[i] = 0ull; }
    float hp1A, hp1B, hp2A = 0.0f, hp2B = 0.0f;
    __syncthreads();

    // ---- prologue: h1[0] = GRU1(gi0[0], 0) ----
    {
        const float4 gA = pw[0], gB = pw[32];
        const float rA = sig_pre(gA.x + bh0r);
        const float rB = sig_pre(gB.x + bh0r);
        const float zA = sig_pre(gA.y + bh0z);
        const float zB = sig_pre(gB.y + bh0z);
        const float nA = tanhapx(fmaf(rA, bh0n, gA.z));
        const float nB = tanhapx(fmaf(rB, bh0n, gB.z));
        hp1A = nA - zA * nA;
        hp1B = nB - zB * nB;
        if (sub < HID) { s_h1[grp_l][0][u] = hp1A; s_h1[grp_l][1][u] = hp1B; }
        __syncwarp();
        const ulonglong2* pa = (const ulonglong2*)s_h1[grp_l][0];
        const ulonglong2* pb = (const ulonglong2*)s_h1[grp_l][1];
        const ulonglong2 a0 = pa[0], a1 = pa[1], a2 = pa[2];
        const ulonglong2 b0 = pb[0], b1 = pb[1], b2 = pb[2];
        H1A[0] = a0.x; H1A[1] = a0.y; H1A[2] = a1.x;
        H1A[3] = a1.y; H1A[4] = a2.x; H1A[5] = a2.y;
        H1B[0] = b0.x; H1B[1] = b0.y; H1B[2] = b1.x;
        H1B[3] = b1.y; H1B[4] = b2.x; H1B[5] = b2.y;
    }

    // gi for t+1 = 1 (consumed by layer1 inside iteration t=0)
    float4 gA = pw[64], gB = pw[96];

#pragma unroll 1
    for (int t = 0; t < SEQ; ++t) {
        const size_t tn = (size_t)((t + 2 < SEQ) ? (t + 2) : SEQ - 1) * 64;
        const float4 gA_n = pw[tn];
        const float4 gB_n = pw[tn + 32];

        // ======== layer 2 @ t (H1=h1[t], H2=h2[t-1])  +  layer 1 @ t+1 ========
        ull prA = pb2r, pzA = pb2z, pnA = pb2hn, piA = pb2in;
        ull prB = pb2r, pzB = pb2z, pnB = pb2hn, piB = pb2in;
        ull qrA = fpack(gA.x, bh0r), qzA = fpack(gA.y, bh0z), qnA = pbh0n;
        ull qrB = fpack(gB.x, bh0r), qzB = fpack(gB.y, bh0z), qnB = pbh0n;

#pragma unroll
        for (int i = 0; i < 6; ++i) {
            prA = ffma2(H2A[i], whh1[0][i], prA); prB = ffma2(H2B[i], whh1[0][i], prB);
            pzA = ffma2(H2A[i], whh1[1][i], pzA); pzB = ffma2(H2B[i], whh1[1][i], pzB);
            pnA = ffma2(H2A[i], whh1[2][i], pnA); pnB = ffma2(H2B[i], whh1[2][i], pnB);
            prA = ffma2(H1A[i], wih1[0][i], prA); prB = ffma2(H1B[i], wih1[0][i], prB);
            pzA = ffma2(H1A[i], wih1[1][i], pzA); pzB = ffma2(H1B[i], wih1[1][i], pzB);
            piA = ffma2(H1A[i], wih1[2][i], piA); piB = ffma2(H1B[i], wih1[2][i], piB);
            qrA = ffma2(H1A[i], whh0[0][i], qrA); qrB = ffma2(H1B[i], whh0[0][i], qrB);
            qzA = ffma2(H1A[i], whh0[1][i], qzA); qzB = ffma2(H1B[i], whh0[1][i], qzB);
            qnA = ffma2(H1A[i], whh0[2][i], qnA); qnB = ffma2(H1B[i], whh0[2][i], qnB);
        }

        // layer2 activations -> h2[t]
        const float r2A = sig_pre(f2sum(prA));
        const float r2B = sig_pre(f2sum(prB));
        const float z2A = sig_pre(f2sum(pzA));
        const float z2B = sig_pre(f2sum(pzB));
        const float n2A = tanhapx(fmaf(r2A, f2sum(pnA), f2sum(piA)));
        const float n2B = tanhapx(fmaf(r2B, f2sum(pnB), f2sum(piB)));
        const float hn2A = fmaf(z2A, hp2A - n2A, n2A);
        const float hn2B = fmaf(z2B, hp2B - n2B, n2B);
        hp2A = hn2A; hp2B = hn2B;

        // layer1 activations -> h1[t+1]
        const float r1A = sig_pre(f2sum(qrA));
        const float r1B = sig_pre(f2sum(qrB));
        const float z1A = sig_pre(f2sum(qzA));
        const float z1B = sig_pre(f2sum(qzB));
        const float n1A = tanhapx(fmaf(r1A, f2sum(qnA), gA.z));
        const float n1B = tanhapx(fmaf(r1B, f2sum(qnB), gB.z));
        const float hn1A = fmaf(z1A, hp1A - n1A, n1A);
        const float hn1B = fmaf(z1B, hp1B - n1B, n1B);
        hp1A = hn1A; hp1B = hn1B;

        // ======== combined exchange ========
        if (sub < HID) {
            s_h1[grp_l][0][u] = hn1A; s_h1[grp_l][1][u] = hn1B;
            s_h2[grp_l][0][u] = hn2A; s_h2[grp_l][1][u] = hn2B;
        }
        __syncwarp();
        {
            const ulonglong2* pa = (const ulonglong2*)s_h1[grp_l][0];
            const ulonglong2* pb = (const ulonglong2*)s_h1[grp_l][1];
            const ulonglong2 a0 = pa[0], a1 = pa[1], a2 = pa[2];
            const ulonglong2 b0 = pb[0], b1 = pb[1], b2 = pb[2];
            H1A[0] = a0.x; H1A[1] = a0.y; H1A[2] = a1.x;
            H1A[3] = a1.y; H1A[4] = a2.x; H1A[5] = a2.y;
            H1B[0] = b0.x; H1B[1] = b0.y; H1B[2] = b1.x;
            H1B[3] = b1.y; H1B[4] = b2.x; H1B[5] = b2.y;
        }
        {
            const ulonglong2* pa = (const ulonglong2*)s_h2[grp_l][0];
            const ulonglong2* pb = (const ulonglong2*)s_h2[grp_l][1];
            const ulonglong2 a0 = pa[0], a1 = pa[1], a2 = pa[2];
            const ulonglong2 b0 = pb[0], b1 = pb[1], b2 = pb[2];
            H2A[0] = a0.x; H2A[1] = a0.y; H2A[2] = a1.x;
            H2A[3] = a1.y; H2A[4] = a2.x; H2A[5] = a2.y;
            H2B[0] = b0.x; H2B[1] = b0.y; H2B[2] = b1.x;
            H2B[3] = b1.y; H2B[4] = b2.x; H2B[5] = b2.y;
        }

        // ======== fc(h2[t]) on idle lanes 12 (A) / 13 (B) ========
        if (sub >= 12 && sub < 14) {
            const ull* hh = (sub == 12) ? H2A : H2B;
            ull acc = fpack(fcb, 0.0f);
#pragma unroll
            for (int i = 0; i < 6; ++i)
                acc = ffma2(hh[i], *(const ull*)&s_fcw[2 * i], acc);
            out[(size_t)((sub == 12) ? bA : bB) * SEQ + t] = f2sum(acc);
        }

        gA = gA_n; gB = gB_n;
    }
}

extern "C" void kernel_launch(void* const* d_in, const int* in_sizes, int n_in,
                              void* d_out, int out_size) {
    const float* x     = (const float*)d_in[0];
    const float* w_ih0 = (const float*)d_in[1];
    const float* w_hh0 = (const float*)d_in[2];
    const float* b_ih0 = (const float*)d_in[3];
    const float* b_hh0 = (const float*)d_in[4];
    const float* w_ih1 = (const float*)d_in[5];
    const float* w_hh1 = (const float*)d_in[6];
    const float* b_ih1 = (const float*)d_in[7];
    const float* b_hh1 = (const float*)d_in[8];
    const float* fc_w  = (const float*)d_in[9];
    const float* fc_b  = (const float*)d_in[10];
    float* out = (float*)d_out;

    gi0_kernel<<<NWARP, 128>>>(x, w_ih0, b_ih0);
    gru_scan_kernel<<<S_GRID, S_THREADS>>>(w_hh0, b_hh0, w_ih1, w_hh1,
                                           b_ih1, b_hh1, fc_w, fc_b, out);
}